// round 3
// baseline (speedup 1.0000x reference)
#include <cuda_runtime.h>
#include <math.h>

#define N_NODES 100000
#define F_IN    128
#define HID     64
#define NODES_PER_CTA 128
#define XPAD    132   // 128 nodes padded (multiple of 4 for LDS.128 alignment)

typedef unsigned long long ull;

// Combined (summed) K=1 diffusion weights, built once per launch by prep_kernel.
__device__ float g_Wz[F_IN * HID];
__device__ float g_Wh[F_IN * HID];

// Wz/Wh shape (2,1,192,64) row-major; only rows 0..127 matter (H0 == 0).
__global__ void prep_kernel(const float* __restrict__ Wz,
                            const float* __restrict__ Wh) {
    int idx = blockIdx.x * blockDim.x + threadIdx.x;
    if (idx < F_IN * HID) {
        int k = idx / HID;
        int j = idx % HID;
        int o0 = k * HID + j;
        int o1 = 192 * HID + k * HID + j;
        g_Wz[idx] = Wz[o0] + Wz[o1];
        g_Wh[idx] = Wh[o0] + Wh[o1];
    }
}

// Packed fp32x2 FMA (Blackwell FFMA2) — 2 fp32 lanes per FMA slot.
__device__ __forceinline__ ull ffma2(ull a, ull b, ull c) {
    ull d;
    asm("fma.rn.f32x2 %0, %1, %2, %3;" : "=l"(d) : "l"(a), "l"(b), "l"(c));
    return d;
}
__device__ __forceinline__ ull dup2(float s) {
    ull d;
    asm("mov.b64 %0, {%1, %1};" : "=l"(d) : "r"(__float_as_uint(s)));
    return d;
}
__device__ __forceinline__ void unpack2(ull p, float& lo, float& hi) {
    unsigned int l, h;
    asm("mov.b64 {%0, %1}, %2;" : "=r"(l), "=r"(h) : "l"(p));
    lo = __uint_as_float(l);
    hi = __uint_as_float(h);
}

// CTA: 256 threads = 16 tx (col groups of 4) x 16 ty (node groups of 8).
// Tile: 128 nodes x 64 cols. Thread: 8 nodes x 4 cols x 2 matrices,
// accumulated as f32x2 node pairs -> 32 packed accumulators.
__global__ void __launch_bounds__(256, 1)
gcn_kernel(const float* __restrict__ x,
           const float* __restrict__ bz,
           const float* __restrict__ bh,
           const float* __restrict__ wlin,
           const float* __restrict__ blin,
           float* __restrict__ out) {
    extern __shared__ float smem[];
    float* sWz = smem;                          // 128*64
    float* sWh = sWz + F_IN * HID;              // 128*64
    float* sX  = sWh + F_IN * HID;              // 128 k x XPAD nodes
    float* sBz = sX + F_IN * XPAD;              // 64
    float* sBh = sBz + HID;                     // 64
    float* sWl = sBh + HID;                     // 64

    const int tid = threadIdx.x;
    const int tx = tid & 15;        // col group: cols tx*4 .. tx*4+3
    const int ty = tid >> 4;        // node group: nodes ty*8 .. ty*8+7

    // Stage weights (hot in L2) — vectorized.
    {
        const float4* gz = reinterpret_cast<const float4*>(g_Wz);
        const float4* gh = reinterpret_cast<const float4*>(g_Wh);
        float4* dz = reinterpret_cast<float4*>(sWz);
        float4* dh = reinterpret_cast<float4*>(sWh);
        #pragma unroll
        for (int i = tid; i < (F_IN * HID) / 4; i += 256) {
            dz[i] = gz[i];
            dh[i] = gh[i];
        }
    }
    if (tid < HID) {
        sBz[tid] = bz[tid];
        sBh[tid] = bh[tid];
        sWl[tid] = wlin[tid];
    }

    const int node0 = blockIdx.x * NODES_PER_CTA;

    // Stage x tile transposed: sX[k][node_local]; coalesced LDG over k.
    for (int i = tid; i < NODES_PER_CTA * F_IN; i += 256) {
        int nl = i >> 7;            // node_local 0..127
        int k  = i & 127;
        int node = node0 + nl;
        float v = (node < N_NODES) ? x[node * F_IN + k] : 0.0f;
        sX[k * XPAD + nl] = v;
    }
    __syncthreads();

    ull azp[4][4], ahp[4][4];       // [node_pair][col]
    #pragma unroll
    for (int np = 0; np < 4; np++)
        #pragma unroll
        for (int c = 0; c < 4; c++) { azp[np][c] = 0ull; ahp[np][c] = 0ull; }

    // Main loop: per k-step 4x LDS.128, 8 dup-packs, 32 FFMA2 (=64 FMAs).
    #pragma unroll 2
    for (int k = 0; k < F_IN; k++) {
        const ulonglong2 a0 = *reinterpret_cast<const ulonglong2*>(&sX[k * XPAD + ty * 8]);
        const ulonglong2 a1 = *reinterpret_cast<const ulonglong2*>(&sX[k * XPAD + ty * 8 + 4]);
        const float4 wz = *reinterpret_cast<const float4*>(&sWz[k * HID + tx * 4]);
        const float4 wh = *reinterpret_cast<const float4*>(&sWh[k * HID + tx * 4]);
        ull ap[4] = {a0.x, a0.y, a1.x, a1.y};
        ull wzd[4] = {dup2(wz.x), dup2(wz.y), dup2(wz.z), dup2(wz.w)};
        ull whd[4] = {dup2(wh.x), dup2(wh.y), dup2(wh.z), dup2(wh.w)};
        #pragma unroll
        for (int np = 0; np < 4; np++) {
            #pragma unroll
            for (int c = 0; c < 4; c++) {
                azp[np][c] = ffma2(ap[np], wzd[c], azp[np][c]);
                ahp[np][c] = ffma2(ap[np], whd[c], ahp[np][c]);
            }
        }
    }

    // Fused epilogue: h = relu((1 - sigmoid(az+bz)) * tanh(ah+bh));
    // p[r] = sum_c h * wlin[c].  1 - sigmoid(t) = 1/(1+exp(t)).
    float p[8];
    #pragma unroll
    for (int r = 0; r < 8; r++) p[r] = 0.0f;

    #pragma unroll
    for (int np = 0; np < 4; np++) {
        #pragma unroll
        for (int c = 0; c < 4; c++) {
            const int j = tx * 4 + c;
            float zl, zh, hl, hh;
            unpack2(azp[np][c], zl, zh);
            unpack2(ahp[np][c], hl, hh);
            const float wj = sWl[j], bzj = sBz[j], bhj = sBh[j];
            {
                float omz = 1.0f / (1.0f + expf(zl + bzj));
                float ht  = tanhf(hl + bhj);
                float h   = fmaxf(omz * ht, 0.0f);
                p[2 * np + 0] = fmaf(h, wj, p[2 * np + 0]);
            }
            {
                float omz = 1.0f / (1.0f + expf(zh + bzj));
                float ht  = tanhf(hh + bhj);
                float h   = fmaxf(omz * ht, 0.0f);
                p[2 * np + 1] = fmaf(h, wj, p[2 * np + 1]);
            }
        }
    }

    // Reduce 16 col-group partials per node: 16-lane shuffle groups (same ty).
    #pragma unroll
    for (int off = 8; off > 0; off >>= 1) {
        #pragma unroll
        for (int r = 0; r < 8; r++)
            p[r] += __shfl_down_sync(0xffffffffu, p[r], off, 16);
    }

    if (tx == 0) {
        const float bl = blin[0];
        #pragma unroll
        for (int r = 0; r < 8; r++) {
            int node = node0 + ty * 8 + r;
            if (node < N_NODES) out[node] = p[r] + bl;
        }
    }
}

extern "C" void kernel_launch(void* const* d_in, const int* in_sizes, int n_in,
                              void* d_out, int out_size) {
    // metadata order: x, edge_index, edge_weight, Wz, bz, Wr, br, Wh, bh, Wlin, blin
    const float* x    = (const float*)d_in[0];
    const float* Wz   = (const float*)d_in[3];
    const float* bz   = (const float*)d_in[4];
    const float* Wh   = (const float*)d_in[7];
    const float* bh   = (const float*)d_in[8];
    const float* wlin = (const float*)d_in[9];
    const float* blin = (const float*)d_in[10];
    float* out = (float*)d_out;

    prep_kernel<<<(F_IN * HID + 255) / 256, 256>>>(Wz, Wh);

    size_t smem_bytes = (size_t)(2 * F_IN * HID + F_IN * XPAD + 3 * HID) * sizeof(float);
    cudaFuncSetAttribute(gcn_kernel, cudaFuncAttributeMaxDynamicSharedMemorySize,
                         (int)smem_bytes);
    int grid = (N_NODES + NODES_PER_CTA - 1) / NODES_PER_CTA;
    gcn_kernel<<<grid, 256, smem_bytes>>>(x, bz, bh, wlin, blin, out);
}

// round 7
// speedup vs baseline: 1.2262x; 1.2262x over previous
#include <cuda_runtime.h>
#include <math.h>

#define N_NODES 100000
#define F_IN    128
#define HID     64
#define NODES_PER_CTA 64
#define XPAD    68   // 64 nodes padded (multiple of 4 for LDS.128 alignment)

typedef unsigned long long ull;

// Combined (summed) K=1 diffusion weights, built once per launch by prep_kernel.
__device__ float g_Wz[F_IN * HID];
__device__ float g_Wh[F_IN * HID];

// Wz/Wh shape (2,1,192,64) row-major; only rows 0..127 matter (H0 == 0).
__global__ void prep_kernel(const float* __restrict__ Wz,
                            const float* __restrict__ Wh) {
    int idx = blockIdx.x * blockDim.x + threadIdx.x;
    if (idx < F_IN * HID) {
        int k = idx / HID;
        int j = idx % HID;
        int o0 = k * HID + j;
        int o1 = 192 * HID + k * HID + j;
        g_Wz[idx] = Wz[o0] + Wz[o1];
        g_Wh[idx] = Wh[o0] + Wh[o1];
    }
}

// Packed fp32x2 FMA (Blackwell FFMA2) — 2 fp32 lanes per FMA slot.
__device__ __forceinline__ ull ffma2(ull a, ull b, ull c) {
    ull d;
    asm("fma.rn.f32x2 %0, %1, %2, %3;" : "=l"(d) : "l"(a), "l"(b), "l"(c));
    return d;
}
__device__ __forceinline__ ull dup2(float s) {
    ull d;
    asm("mov.b64 %0, {%1, %1};" : "=l"(d) : "r"(__float_as_uint(s)));
    return d;
}
__device__ __forceinline__ void unpack2(ull p, float& lo, float& hi) {
    unsigned int l, h;
    asm("mov.b64 {%0, %1}, %2;" : "=r"(l), "=r"(h) : "l"(p));
    lo = __uint_as_float(l);
    hi = __uint_as_float(h);
}

// CTA: 256 threads = 16 tx (col groups of 4) x 16 ty (node groups of 4).
// Tile: 64 nodes x 64 cols. Thread: 4 nodes x 4 cols x 2 matrices, with
// f32x2 packing along the COLUMN dimension -> weight float4 loads are
// already two packed col-pair ulls (no dup); only the 4 a-scalars get dup2.
// 16 packed accumulators = 64 scalar FMAs per k per thread.
__global__ void __launch_bounds__(256, 2)
gcn_kernel(const float* __restrict__ x,
           const float* __restrict__ bz,
           const float* __restrict__ bh,
           const float* __restrict__ wlin,
           const float* __restrict__ blin,
           float* __restrict__ out) {
    extern __shared__ float smem[];
    float* sWz = smem;                          // 128*64
    float* sWh = sWz + F_IN * HID;              // 128*64
    float* sX  = sWh + F_IN * HID;              // 128 k x XPAD nodes
    float* sBz = sX + F_IN * XPAD;              // 64
    float* sBh = sBz + HID;                     // 64
    float* sWl = sBh + HID;                     // 64

    const int tid = threadIdx.x;
    const int tx = tid & 15;        // col group: cols tx*4 .. tx*4+3
    const int ty = tid >> 4;        // node group: nodes ty*4 .. ty*4+3

    // Stage weights (hot in L2) — vectorized.
    {
        const float4* gz = reinterpret_cast<const float4*>(g_Wz);
        const float4* gh = reinterpret_cast<const float4*>(g_Wh);
        float4* dz = reinterpret_cast<float4*>(sWz);
        float4* dh = reinterpret_cast<float4*>(sWh);
        #pragma unroll
        for (int i = tid; i < (F_IN * HID) / 4; i += 256) {
            dz[i] = gz[i];
            dh[i] = gh[i];
        }
    }
    if (tid < HID) {
        sBz[tid] = bz[tid];
        sBh[tid] = bh[tid];
        sWl[tid] = wlin[tid];
    }

    const int node0 = blockIdx.x * NODES_PER_CTA;

    // Stage x tile transposed: sX[k][node_local]; coalesced LDG over k.
    for (int i = tid; i < NODES_PER_CTA * F_IN; i += 256) {
        int nl = i >> 7;            // node_local 0..63
        int k  = i & 127;
        int node = node0 + nl;
        float v = (node < N_NODES) ? x[node * F_IN + k] : 0.0f;
        sX[k * XPAD + nl] = v;
    }
    __syncthreads();

    ull az[4][2], ah[4][2];         // [node][col_pair]
    #pragma unroll
    for (int r = 0; r < 4; r++)
        #pragma unroll
        for (int cp = 0; cp < 2; cp++) { az[r][cp] = 0ull; ah[r][cp] = 0ull; }

    // Main loop: per k-step 3x LDS.128, 4 dup-packs, 16 FFMA2 (= 64 FMAs).
    #pragma unroll 4
    for (int k = 0; k < F_IN; k++) {
        const float4 a4 = *reinterpret_cast<const float4*>(&sX[k * XPAD + ty * 4]);
        const ulonglong2 wz2 = *reinterpret_cast<const ulonglong2*>(&sWz[k * HID + tx * 4]);
        const ulonglong2 wh2 = *reinterpret_cast<const ulonglong2*>(&sWh[k * HID + tx * 4]);
        const ull ad[4] = {dup2(a4.x), dup2(a4.y), dup2(a4.z), dup2(a4.w)};
        const ull wzp[2] = {wz2.x, wz2.y};
        const ull whp[2] = {wh2.x, wh2.y};
        #pragma unroll
        for (int r = 0; r < 4; r++) {
            #pragma unroll
            for (int cp = 0; cp < 2; cp++) {
                az[r][cp] = ffma2(ad[r], wzp[cp], az[r][cp]);
                ah[r][cp] = ffma2(ad[r], whp[cp], ah[r][cp]);
            }
        }
    }

    // Fused epilogue: h = relu((1 - sigmoid(az+bz)) * tanh(ah+bh));
    // p[r] = sum_c h * wlin[c].  1 - sigmoid(t) = 1/(1+exp(t)).
    float p[4] = {0.0f, 0.0f, 0.0f, 0.0f};
    #pragma unroll
    for (int r = 0; r < 4; r++) {
        #pragma unroll
        for (int cp = 0; cp < 2; cp++) {
            const int j0 = tx * 4 + 2 * cp;
            float z0, z1, h0, h1;
            unpack2(az[r][cp], z0, z1);
            unpack2(ah[r][cp], h0, h1);
            {
                float omz = 1.0f / (1.0f + expf(z0 + sBz[j0]));
                float ht  = tanhf(h0 + sBh[j0]);
                float h   = fmaxf(omz * ht, 0.0f);
                p[r] = fmaf(h, sWl[j0], p[r]);
            }
            {
                float omz = 1.0f / (1.0f + expf(z1 + sBz[j0 + 1]));
                float ht  = tanhf(h1 + sBh[j0 + 1]);
                float h   = fmaxf(omz * ht, 0.0f);
                p[r] = fmaf(h, sWl[j0 + 1], p[r]);
            }
        }
    }

    // Reduce 16 col-group partials per node: 16-lane shuffle groups (same ty).
    #pragma unroll
    for (int off = 8; off > 0; off >>= 1) {
        #pragma unroll
        for (int r = 0; r < 4; r++)
            p[r] += __shfl_down_sync(0xffffffffu, p[r], off, 16);
    }

    if (tx == 0) {
        const float bl = blin[0];
        #pragma unroll
        for (int r = 0; r < 4; r++) {
            int node = node0 + ty * 4 + r;
            if (node < N_NODES) out[node] = p[r] + bl;
        }
    }
}

extern "C" void kernel_launch(void* const* d_in, const int* in_sizes, int n_in,
                              void* d_out, int out_size) {
    // metadata order: x, edge_index, edge_weight, Wz, bz, Wr, br, Wh, bh, Wlin, blin
    const float* x    = (const float*)d_in[0];
    const float* Wz   = (const float*)d_in[3];
    const float* bz   = (const float*)d_in[4];
    const float* Wh   = (const float*)d_in[7];
    const float* bh   = (const float*)d_in[8];
    const float* wlin = (const float*)d_in[9];
    const float* blin = (const float*)d_in[10];
    float* out = (float*)d_out;

    prep_kernel<<<(F_IN * HID + 255) / 256, 256>>>(Wz, Wh);

    size_t smem_bytes = (size_t)(2 * F_IN * HID + F_IN * XPAD + 3 * HID) * sizeof(float);
    cudaFuncSetAttribute(gcn_kernel, cudaFuncAttributeMaxDynamicSharedMemorySize,
                         (int)smem_bytes);
    int grid = (N_NODES + NODES_PER_CTA - 1) / NODES_PER_CTA;
    gcn_kernel<<<grid, 256, smem_bytes>>>(x, bz, bh, wlin, blin, out);
}

// round 16
// speedup vs baseline: 2.0327x; 1.6577x over previous
#include <cuda_runtime.h>
#include <cuda_bf16.h>
#include <cstdint>

#define N_NODES 100000
#define KDIM    128
#define NB      128      // B rows = concat [Wz(64) | Wh(64)]
#define HID     64
#define M_TILE  128
#define THREADS 256
#define SW      68       // row stride in 32-bit words (= 136 bf16, conflict-free)

// ---------------- smem layout (bytes) ----------------
#define OFF_A_HI 0
#define OFF_A_LO 34816
#define OFF_B_HI 69632
#define OFF_B_LO 104448
#define OFF_BZ   139264
#define OFF_BH   139520
#define OFF_WL   139776
#define SMEM_TOTAL 140032

// Weights pre-folded + bf16 hi/lo split, padded [n][136] bf16 layout.
// 128 rows * 272 B = 34816 B = 2176 uint4 each.
__device__ uint4 g_Bhi[2176];
__device__ uint4 g_Blo[2176];

// ---------------- prep: fold + split weights ----------------
// Wz/Wh shape (2,1,192,64); only input rows 0..127 matter (H0 == 0).
// B[n][k] = effective weight w[k][n%64] of (n<64 ? Wz : Wh).
__global__ void prep_kernel(const float* __restrict__ Wz,
                            const float* __restrict__ Wh) {
    int idx = blockIdx.x * blockDim.x + threadIdx.x;
    if (idx >= NB * KDIM) return;
    int n = idx >> 7, k = idx & 127;
    const float* W = (n < 64) ? Wz : Wh;
    int col = n & 63;
    float v = W[k * 64 + col] + W[192 * 64 + k * 64 + col];
    __nv_bfloat16 hi = __float2bfloat16(v);
    __nv_bfloat16 lo = __float2bfloat16(v - __bfloat162float(hi));
    size_t off = (size_t)n * 272 + (size_t)k * 2;   // bytes within padded row
    *reinterpret_cast<__nv_bfloat16*>(reinterpret_cast<char*>(g_Bhi) + off) = hi;
    *reinterpret_cast<__nv_bfloat16*>(reinterpret_cast<char*>(g_Blo) + off) = lo;
}

// m16n8k16 bf16 MMA, fp32 accumulate (family-portable HMMA path).
__device__ __forceinline__ void mma16816(float* d,
                                         uint32_t a0, uint32_t a1, uint32_t a2, uint32_t a3,
                                         uint32_t b0, uint32_t b1) {
    asm("mma.sync.aligned.m16n8k16.row.col.f32.bf16.bf16.f32 "
        "{%0,%1,%2,%3}, {%4,%5,%6,%7}, {%8,%9}, {%0,%1,%2,%3};"
        : "+f"(d[0]), "+f"(d[1]), "+f"(d[2]), "+f"(d[3])
        : "r"(a0), "r"(a1), "r"(a2), "r"(a3), "r"(b0), "r"(b1));
}

__device__ __forceinline__ uint32_t pack_bf16x2(float x, float y) {
    __nv_bfloat16 h0 = __float2bfloat16(x);
    __nv_bfloat16 h1 = __float2bfloat16(y);
    return (uint32_t)__bfloat16_as_ushort(h0) | ((uint32_t)__bfloat16_as_ushort(h1) << 16);
}

// ---------------- main: HMMA dual-GEMM + fused GRU epilogue ----------------
__global__ void __launch_bounds__(THREADS, 1)
gcn_kernel(const float* __restrict__ x,
           const float* __restrict__ bz,
           const float* __restrict__ bh,
           const float* __restrict__ wlin,
           const float* __restrict__ blin,
           float* __restrict__ out) {
    extern __shared__ char smem[];
    uint32_t* Ahi = reinterpret_cast<uint32_t*>(smem + OFF_A_HI);
    uint32_t* Alo = reinterpret_cast<uint32_t*>(smem + OFF_A_LO);
    uint32_t* Bhi = reinterpret_cast<uint32_t*>(smem + OFF_B_HI);
    uint32_t* Blo = reinterpret_cast<uint32_t*>(smem + OFF_B_LO);
    float* sBz = reinterpret_cast<float*>(smem + OFF_BZ);
    float* sBh = reinterpret_cast<float*>(smem + OFF_BH);
    float* sWl = reinterpret_cast<float*>(smem + OFF_WL);

    const int tid  = threadIdx.x;
    const int wid  = tid >> 5;
    const int lane = tid & 31;
    const int node0 = blockIdx.x * M_TILE;

    // Stage weights: straight 16B copies (already split + padded in gmem).
    {
        uint4* dh = reinterpret_cast<uint4*>(smem + OFF_B_HI);
        uint4* dl = reinterpret_cast<uint4*>(smem + OFF_B_LO);
        #pragma unroll
        for (int i = tid; i < 2176; i += THREADS) {
            dh[i] = g_Bhi[i];
            dl[i] = g_Blo[i];
        }
    }
    if (tid < HID) {
        sBz[tid] = bz[tid];
        sBh[tid] = bh[tid];
        sWl[tid] = wlin[tid];
    }

    // Stage x tile: fp32 -> bf16 hi/lo words into padded layout. Coalesced LDG.64.
    for (int i = tid; i < M_TILE * (KDIM / 2); i += THREADS) {
        int row = i >> 6;          // 64 word-pairs per row
        int kp  = i & 63;          // word index = k/2
        int node = node0 + row;
        float vx = 0.0f, vy = 0.0f;
        if (node < N_NODES) {
            float2 v = *reinterpret_cast<const float2*>(x + (size_t)node * KDIM + kp * 2);
            vx = v.x; vy = v.y;
        }
        __nv_bfloat16 h0 = __float2bfloat16(vx);
        __nv_bfloat16 h1 = __float2bfloat16(vy);
        float r0 = vx - __bfloat162float(h0);
        float r1 = vy - __bfloat162float(h1);
        Ahi[row * SW + kp] = (uint32_t)__bfloat16_as_ushort(h0) |
                             ((uint32_t)__bfloat16_as_ushort(h1) << 16);
        Alo[row * SW + kp] = pack_bf16x2(r0, r1);
    }
    __syncthreads();

    // Warp w: rows w*16 .. w*16+15, all 128 output cols (16 n-tiles).
    // Fragment lane mapping: g = lane/4 (row in octet), tig = lane%4 (k-pair).
    const int g = lane >> 2, tig = lane & 3;
    const int rA = wid * 16 + g;

    float acc[16][4];
    #pragma unroll
    for (int nt = 0; nt < 16; nt++)
        #pragma unroll
        for (int i = 0; i < 4; i++) acc[nt][i] = 0.0f;

    for (int ks = 0; ks < 8; ks++) {
        const int kb = ks * 8 + tig;
        const uint32_t ah0 = Ahi[rA * SW + kb];
        const uint32_t ah1 = Ahi[(rA + 8) * SW + kb];
        const uint32_t ah2 = Ahi[rA * SW + kb + 4];
        const uint32_t ah3 = Ahi[(rA + 8) * SW + kb + 4];
        const uint32_t al0 = Alo[rA * SW + kb];
        const uint32_t al1 = Alo[(rA + 8) * SW + kb];
        const uint32_t al2 = Alo[rA * SW + kb + 4];
        const uint32_t al3 = Alo[(rA + 8) * SW + kb + 4];
        #pragma unroll
        for (int nt = 0; nt < 16; nt++) {
            const int nb = (nt * 8 + g) * SW + kb;
            const uint32_t bh0 = Bhi[nb];
            const uint32_t bh1 = Bhi[nb + 4];
            mma16816(acc[nt], ah0, ah1, ah2, ah3, bh0, bh1);   // hi*hi
            mma16816(acc[nt], al0, al1, al2, al3, bh0, bh1);   // lo*hi
            const uint32_t bl0 = Blo[nb];
            const uint32_t bl1 = Blo[nb + 4];
            mma16816(acc[nt], ah0, ah1, ah2, ah3, bl0, bl1);   // hi*lo
        }
    }

    // Epilogue. Lane holds D for rows {rA, rA+8}, cols j = nt*8 + tig*2 + c
    // (nt 0..7 -> az = cols 0..63; nt+8 -> ah = cols 64..127).
    // h = relu((1 - sigmoid(az+bz)) * tanh(ah+bh)); p = sum_j h * wlin[j].
    float p0 = 0.0f, p1 = 0.0f;
    #pragma unroll
    for (int nt = 0; nt < 8; nt++) {
        #pragma unroll
        for (int c = 0; c < 2; c++) {
            const int j = nt * 8 + tig * 2 + c;
            const float bzj = sBz[j], bhj = sBh[j], wj = sWl[j];
            {   // row rA
                float t = acc[nt][c] + bzj;
                float u = acc[nt + 8][c] + bhj;
                float omz = __fdividef(1.0f, 1.0f + __expf(t));
                float th;
                asm("tanh.approx.f32 %0, %1;" : "=f"(th) : "f"(u));
                p0 = fmaf(fmaxf(omz * th, 0.0f), wj, p0);
            }
            {   // row rA+8
                float t = acc[nt][c + 2] + bzj;
                float u = acc[nt + 8][c + 2] + bhj;
                float omz = __fdividef(1.0f, 1.0f + __expf(t));
                float th;
                asm("tanh.approx.f32 %0, %1;" : "=f"(th) : "f"(u));
                p1 = fmaf(fmaxf(omz * th, 0.0f), wj, p1);
            }
        }
    }
    // Reduce the 4 k-pair lanes (tig) of each row group.
    p0 += __shfl_xor_sync(0xffffffffu, p0, 1);
    p0 += __shfl_xor_sync(0xffffffffu, p0, 2);
    p1 += __shfl_xor_sync(0xffffffffu, p1, 1);
    p1 += __shfl_xor_sync(0xffffffffu, p1, 2);

    if (tig == 0) {
        const float bl = blin[0];
        int n0 = node0 + rA;
        if (n0 < N_NODES) out[n0] = p0 + bl;
        int n1 = node0 + rA + 8;
        if (n1 < N_NODES) out[n1] = p1 + bl;
    }
}

extern "C" void kernel_launch(void* const* d_in, const int* in_sizes, int n_in,
                              void* d_out, int out_size) {
    // metadata order: x, edge_index, edge_weight, Wz, bz, Wr, br, Wh, bh, Wlin, blin
    const float* x    = (const float*)d_in[0];
    const float* Wz   = (const float*)d_in[3];
    const float* bz   = (const float*)d_in[4];
    const float* Wh   = (const float*)d_in[7];
    const float* bh   = (const float*)d_in[8];
    const float* wlin = (const float*)d_in[9];
    const float* blin = (const float*)d_in[10];
    float* out = (float*)d_out;

    prep_kernel<<<(NB * KDIM + 255) / 256, 256>>>(Wz, Wh);

    cudaFuncSetAttribute(gcn_kernel, cudaFuncAttributeMaxDynamicSharedMemorySize, SMEM_TOTAL);

    int grid = (N_NODES + M_TILE - 1) / M_TILE;
    gcn_kernel<<<grid, THREADS, SMEM_TOTAL>>>(x, bz, bh, wlin, blin, out);
}